// round 3
// baseline (speedup 1.0000x reference)
#include <cuda_runtime.h>
#include <math.h>

#define B 64
#define N 8192
#define M 128
#define EPS 1e-16f
#define EPS_COS 1e-8f

// ---------------- scratch (no allocation allowed) ----------------
__device__ float g_cos[B * N];          // 2 MB
__device__ float g_w[B * N];            // 2 MB
__device__ float g_pr[B * 128 * M];     // 4 MB partial r: [B][128 blocks][M]

// ---------------- kernel 1: cosine similarity, one warp per row ----------------
__global__ void cos_kernel(const float* __restrict__ mem, const float* __restrict__ k) {
    int warp = (blockIdx.x * blockDim.x + threadIdx.x) >> 5;
    int lane = threadIdx.x & 31;
    if (warp >= B * N) return;
    int b = warp >> 13;  // / N

    const float4 m4 = reinterpret_cast<const float4*>(mem + (size_t)warp * M)[lane];
    const float4 k4 = reinterpret_cast<const float4*>(k + b * M)[lane];

    float kx = k4.x + EPS, ky = k4.y + EPS, kz = k4.z + EPS, kw = k4.w + EPS;
    float mx = m4.x + EPS, my = m4.y + EPS, mz = m4.z + EPS, mw = m4.w + EPS;

    float dot = mx * kx + my * ky + mz * kz + mw * kw;
    float nm2 = mx * mx + my * my + mz * mz + mw * mw;
    float nk2 = kx * kx + ky * ky + kz * kz + kw * kw;

    #pragma unroll
    for (int s = 16; s > 0; s >>= 1) {
        dot += __shfl_xor_sync(0xffffffffu, dot, s);
        nm2 += __shfl_xor_sync(0xffffffffu, nm2, s);
        nk2 += __shfl_xor_sync(0xffffffffu, nk2, s);
    }
    if (lane == 0) {
        float nm = fmaxf(sqrtf(nm2), EPS_COS);
        float nk = fmaxf(sqrtf(nk2), EPS_COS);
        g_cos[warp] = dot / (nm * nk);
    }
}

// ---------------- kernel 2: softmax + interpolate + shift + sharpen ----------------
// one block per batch, 1024 threads, 8 elems/thread, wg row lives in shared
__global__ __launch_bounds__(1024) void addr_kernel(
    const float* __restrict__ beta, const float* __restrict__ g,
    const float* __restrict__ s, const float* __restrict__ gamma,
    const float* __restrict__ w_prev)
{
    __shared__ float sw[N];        // 32 KB
    __shared__ float red[32];
    int b = blockIdx.x;
    int tid = threadIdx.x;
    int lane = tid & 31, wid = tid >> 5;

    float betav = beta[b], gv = g[b], gammav = gamma[b];
    float s0 = s[b * 3 + 0], s1 = s[b * 3 + 1], s2 = s[b * 3 + 2];

    // pass A: bc = beta*cos into shared, block-max
    float mx = -1e30f;
    #pragma unroll
    for (int j = 0; j < N / 1024; ++j) {
        int i = tid + j * 1024;
        float v = betav * g_cos[b * N + i];
        sw[i] = v;
        mx = fmaxf(mx, v);
    }
    #pragma unroll
    for (int t = 16; t > 0; t >>= 1) mx = fmaxf(mx, __shfl_xor_sync(0xffffffffu, mx, t));
    if (lane == 0) red[wid] = mx;
    __syncthreads();
    float bmx = red[0];
    #pragma unroll
    for (int w = 1; w < 32; ++w) bmx = fmaxf(bmx, red[w]);

    // pass B: exp + sum
    float sum = 0.f;
    #pragma unroll
    for (int j = 0; j < N / 1024; ++j) {
        int i = tid + j * 1024;
        float ev = expf(sw[i] - bmx);
        sw[i] = ev;
        sum += ev;
    }
    #pragma unroll
    for (int t = 16; t > 0; t >>= 1) sum += __shfl_xor_sync(0xffffffffu, sum, t);
    __syncthreads();
    if (lane == 0) red[wid] = sum;
    __syncthreads();
    float bsum = 0.f;
    #pragma unroll
    for (int w = 0; w < 32; ++w) bsum += red[w];
    float inv = 1.f / bsum;

    // wg = g*wc + (1-g)*w_prev, back into shared
    #pragma unroll
    for (int j = 0; j < N / 1024; ++j) {
        int i = tid + j * 1024;
        sw[i] = gv * (sw[i] * inv) + (1.f - gv) * w_prev[b * N + i];
    }
    __syncthreads();

    // circular shift + pow(gamma); keep in registers, block-sum
    float wloc[N / 1024];
    float sum2 = 0.f;
    #pragma unroll
    for (int j = 0; j < N / 1024; ++j) {
        int i = tid + j * 1024;
        int im1 = (i == 0) ? (N - 1) : (i - 1);
        int ip1 = (i == N - 1) ? 0 : (i + 1);
        float wh = s0 * sw[im1] + s1 * sw[i] + s2 * sw[ip1];
        float ww = powf(wh, gammav);
        wloc[j] = ww;
        sum2 += ww;
    }
    #pragma unroll
    for (int t = 16; t > 0; t >>= 1) sum2 += __shfl_xor_sync(0xffffffffu, sum2, t);
    __syncthreads();
    if (lane == 0) red[wid] = sum2;
    __syncthreads();
    float bsum2 = 0.f;
    #pragma unroll
    for (int w = 0; w < 32; ++w) bsum2 += red[w];
    float inv2 = 1.f / (bsum2 + EPS);

    #pragma unroll
    for (int j = 0; j < N / 1024; ++j) {
        int i = tid + j * 1024;
        g_w[b * N + i] = wloc[j] * inv2;
    }
}

// ---------------- kernel 3: new_mem write + fused partial r ----------------
// grid (128, B), 256 threads; each block: 64 rows of one batch
#define ROWS_PER_BLK 64
__global__ __launch_bounds__(256) void write_kernel(
    const float* __restrict__ mem, const float* __restrict__ e,
    const float* __restrict__ a, float* __restrict__ newmem)
{
    int b = blockIdx.y;
    int blk = blockIdx.x;              // 0..127
    int t = threadIdx.x;
    int m4 = t & 31;                   // float4 index along M
    int grp = t >> 5;                  // 8 row groups

    const float4 e4 = reinterpret_cast<const float4*>(e + b * M)[m4];
    const float4 a4 = reinterpret_cast<const float4*>(a + b * M)[m4];

    int n0 = blk * ROWS_PER_BLK;
    size_t base = ((size_t)b * N + n0) * M;
    const float4* mp = reinterpret_cast<const float4*>(mem + base);
    float4* op = reinterpret_cast<float4*>(newmem + base);
    const float* wp = g_w + b * N + n0;

    float4 racc = make_float4(0.f, 0.f, 0.f, 0.f);
    #pragma unroll
    for (int it = 0; it < ROWS_PER_BLK / 8; ++it) {
        int row = it * 8 + grp;
        float wv = __ldg(wp + row);
        float4 mv = mp[row * 32 + m4];
        float4 o;
        o.x = mv.x * (1.f - wv * e4.x) + wv * a4.x;
        o.y = mv.y * (1.f - wv * e4.y) + wv * a4.y;
        o.z = mv.z * (1.f - wv * e4.z) + wv * a4.z;
        o.w = mv.w * (1.f - wv * e4.w) + wv * a4.w;
        op[row * 32 + m4] = o;
        racc.x += wv * mv.x;
        racc.y += wv * mv.y;
        racc.z += wv * mv.z;
        racc.w += wv * mv.w;
    }

    __shared__ float4 sd[256];
    sd[t] = racc;
    __syncthreads();
    #pragma unroll
    for (int s = 4; s > 0; s >>= 1) {
        if (grp < s) {
            float4 o = sd[t + s * 32];
            sd[t].x += o.x; sd[t].y += o.y; sd[t].z += o.z; sd[t].w += o.w;
        }
        __syncthreads();
    }
    if (grp == 0) {
        reinterpret_cast<float4*>(g_pr + ((size_t)b * 128 + blk) * M)[m4] = sd[t];
    }
}

// ---------------- kernel 4: reduce partial r ----------------
__global__ void reduce_r_kernel(float* __restrict__ r) {
    int idx = blockIdx.x * blockDim.x + threadIdx.x;  // B*M = 8192
    if (idx >= B * M) return;
    int b = idx >> 7;
    int m = idx & 127;
    const float* p = g_pr + (size_t)b * 128 * M + m;
    float sacc = 0.f;
    #pragma unroll 8
    for (int j = 0; j < 128; ++j) sacc += p[j * M];
    r[idx] = sacc;
}

// ---------------- launch ----------------
extern "C" void kernel_launch(void* const* d_in, const int* in_sizes, int n_in,
                              void* d_out, int out_size) {
    const float* memory = (const float*)d_in[0];
    const float* k      = (const float*)d_in[1];
    const float* beta   = (const float*)d_in[2];
    const float* g      = (const float*)d_in[3];
    const float* s      = (const float*)d_in[4];
    const float* gamma  = (const float*)d_in[5];
    const float* w_prev = (const float*)d_in[6];
    const float* e      = (const float*)d_in[7];
    const float* a      = (const float*)d_in[8];

    float* r_out  = (float*)d_out;            // [B, M]
    float* nm_out = (float*)d_out + B * M;    // [B, N, M]

    // kernel 1: one warp per (b,n) row
    cos_kernel<<<(B * N) / 8, 256>>>(memory, k);

    // kernel 2: one block per batch
    addr_kernel<<<B, 1024>>>(beta, g, s, gamma, w_prev);

    // kernel 3: write + partial read reduce
    dim3 grid3(N / ROWS_PER_BLK, B);
    write_kernel<<<grid3, 256>>>(memory, e, a, nm_out);

    // kernel 4: final r
    reduce_r_kernel<<<(B * M + 255) / 256, 256>>>(r_out);
}

// round 4
// speedup vs baseline: 1.0339x; 1.0339x over previous
#include <cuda_runtime.h>
#include <math.h>

#define B 64
#define N 8192
#define M 128
#define EPS 1e-16f
#define EPS_COS 1e-8f

// ---------------- scratch (no allocation allowed) ----------------
__device__ float g_cos[B * N];            // 2 MB
__device__ float g_w[B * N];              // 2 MB
__device__ float g_pr[B * 128 * M];       // 4 MB partial r: [B][128 blocks][M]
__device__ unsigned int g_cnt[B];         // per-batch completion counters

// ---------------- kernel 1: cosine similarity, one warp per row ----------------
__global__ void cos_kernel(const float* __restrict__ mem, const float* __restrict__ k) {
    int warp = (blockIdx.x * blockDim.x + threadIdx.x) >> 5;
    int lane = threadIdx.x & 31;
    if (warp >= B * N) return;
    int b = warp >> 13;  // / N

    const float4 m4 = reinterpret_cast<const float4*>(mem + (size_t)warp * M)[lane];
    const float4 k4 = reinterpret_cast<const float4*>(k + b * M)[lane];

    float kx = k4.x + EPS, ky = k4.y + EPS, kz = k4.z + EPS, kw = k4.w + EPS;
    float mx = m4.x + EPS, my = m4.y + EPS, mz = m4.z + EPS, mw = m4.w + EPS;

    float dot = mx * kx + my * ky + mz * kz + mw * kw;
    float nm2 = mx * mx + my * my + mz * mz + mw * mw;
    float nk2 = kx * kx + ky * ky + kz * kz + kw * kw;

    #pragma unroll
    for (int s = 16; s > 0; s >>= 1) {
        dot += __shfl_xor_sync(0xffffffffu, dot, s);
        nm2 += __shfl_xor_sync(0xffffffffu, nm2, s);
        nk2 += __shfl_xor_sync(0xffffffffu, nk2, s);
    }
    if (lane == 0) {
        float nm = fmaxf(sqrtf(nm2), EPS_COS);
        float nk = fmaxf(sqrtf(nk2), EPS_COS);
        g_cos[warp] = dot / (nm * nk);
    }
}

// ---------------- kernel 2: softmax + interpolate + shift + sharpen ----------------
// one block per batch, 1024 threads, 8 elems/thread, wg row lives in shared
__global__ __launch_bounds__(1024) void addr_kernel(
    const float* __restrict__ beta, const float* __restrict__ g,
    const float* __restrict__ s, const float* __restrict__ gamma,
    const float* __restrict__ w_prev)
{
    __shared__ float sw[N];        // 32 KB
    __shared__ float red[32];
    int b = blockIdx.x;
    int tid = threadIdx.x;
    int lane = tid & 31, wid = tid >> 5;

    // reset the completion counter for the fused reduction in kernel 3
    if (tid == 0) g_cnt[b] = 0;

    float betav = beta[b], gv = g[b], gammav = gamma[b];
    float s0 = s[b * 3 + 0], s1 = s[b * 3 + 1], s2 = s[b * 3 + 2];

    // pass A: bc = beta*cos into shared, block-max
    float mx = -1e30f;
    #pragma unroll
    for (int j = 0; j < N / 1024; ++j) {
        int i = tid + j * 1024;
        float v = betav * g_cos[b * N + i];
        sw[i] = v;
        mx = fmaxf(mx, v);
    }
    #pragma unroll
    for (int t = 16; t > 0; t >>= 1) mx = fmaxf(mx, __shfl_xor_sync(0xffffffffu, mx, t));
    if (lane == 0) red[wid] = mx;
    __syncthreads();
    float bmx = red[0];
    #pragma unroll
    for (int w = 1; w < 32; ++w) bmx = fmaxf(bmx, red[w]);

    // pass B: exp + sum (fast-math exp: rel err ~1e-7, fine vs 1e-3 gate)
    float sum = 0.f;
    #pragma unroll
    for (int j = 0; j < N / 1024; ++j) {
        int i = tid + j * 1024;
        float ev = __expf(sw[i] - bmx);
        sw[i] = ev;
        sum += ev;
    }
    #pragma unroll
    for (int t = 16; t > 0; t >>= 1) sum += __shfl_xor_sync(0xffffffffu, sum, t);
    __syncthreads();
    if (lane == 0) red[wid] = sum;
    __syncthreads();
    float bsum = 0.f;
    #pragma unroll
    for (int w = 0; w < 32; ++w) bsum += red[w];
    float inv = 1.f / bsum;

    // wg = g*wc + (1-g)*w_prev, back into shared
    #pragma unroll
    for (int j = 0; j < N / 1024; ++j) {
        int i = tid + j * 1024;
        sw[i] = gv * (sw[i] * inv) + (1.f - gv) * w_prev[b * N + i];
    }
    __syncthreads();

    // circular shift + pow(gamma); w_hat > 0 always (all inputs positive),
    // so pow(x,y) = exp(y*log(x)) via fast intrinsics is safe.
    float wloc[N / 1024];
    float sum2 = 0.f;
    #pragma unroll
    for (int j = 0; j < N / 1024; ++j) {
        int i = tid + j * 1024;
        int im1 = (i == 0) ? (N - 1) : (i - 1);
        int ip1 = (i == N - 1) ? 0 : (i + 1);
        float wh = s0 * sw[im1] + s1 * sw[i] + s2 * sw[ip1];
        float ww = __expf(gammav * __logf(wh));
        wloc[j] = ww;
        sum2 += ww;
    }
    #pragma unroll
    for (int t = 16; t > 0; t >>= 1) sum2 += __shfl_xor_sync(0xffffffffu, sum2, t);
    __syncthreads();
    if (lane == 0) red[wid] = sum2;
    __syncthreads();
    float bsum2 = 0.f;
    #pragma unroll
    for (int w = 0; w < 32; ++w) bsum2 += red[w];
    float inv2 = 1.f / (bsum2 + EPS);

    #pragma unroll
    for (int j = 0; j < N / 1024; ++j) {
        int i = tid + j * 1024;
        g_w[b * N + i] = wloc[j] * inv2;
    }
}

// ---------------- kernel 3: new_mem write + fused r reduction ----------------
// grid (128, B), 256 threads; each block: 64 rows of one batch.
// Last-finishing block per batch deterministically sums the 128 partials.
#define ROWS_PER_BLK 64
__global__ __launch_bounds__(256) void write_kernel(
    const float* __restrict__ mem, const float* __restrict__ e,
    const float* __restrict__ a, float* __restrict__ newmem,
    float* __restrict__ r_out)
{
    int b = blockIdx.y;
    int blk = blockIdx.x;              // 0..127
    int t = threadIdx.x;
    int m4 = t & 31;                   // float4 index along M
    int grp = t >> 5;                  // 8 row groups

    const float4 e4 = reinterpret_cast<const float4*>(e + b * M)[m4];
    const float4 a4 = reinterpret_cast<const float4*>(a + b * M)[m4];

    int n0 = blk * ROWS_PER_BLK;
    size_t base = ((size_t)b * N + n0) * M;
    const float4* mp = reinterpret_cast<const float4*>(mem + base);
    float4* op = reinterpret_cast<float4*>(newmem + base);
    const float* wp = g_w + b * N + n0;

    float4 racc = make_float4(0.f, 0.f, 0.f, 0.f);
    #pragma unroll
    for (int it = 0; it < ROWS_PER_BLK / 8; ++it) {
        int row = it * 8 + grp;
        float wv = __ldg(wp + row);
        float4 mv = mp[row * 32 + m4];
        float4 o;
        o.x = mv.x * (1.f - wv * e4.x) + wv * a4.x;
        o.y = mv.y * (1.f - wv * e4.y) + wv * a4.y;
        o.z = mv.z * (1.f - wv * e4.z) + wv * a4.z;
        o.w = mv.w * (1.f - wv * e4.w) + wv * a4.w;
        op[row * 32 + m4] = o;
        racc.x += wv * mv.x;
        racc.y += wv * mv.y;
        racc.z += wv * mv.z;
        racc.w += wv * mv.w;
    }

    __shared__ float4 sd[256];
    __shared__ bool is_last;
    sd[t] = racc;
    __syncthreads();
    #pragma unroll
    for (int s = 4; s > 0; s >>= 1) {
        if (grp < s) {
            float4 o = sd[t + s * 32];
            sd[t].x += o.x; sd[t].y += o.y; sd[t].z += o.z; sd[t].w += o.w;
        }
        __syncthreads();
    }
    if (grp == 0) {
        reinterpret_cast<float4*>(g_pr + ((size_t)b * 128 + blk) * M)[m4] = sd[t];
    }

    // make the partial visible, then take a ticket
    __threadfence();
    if (t == 0) {
        unsigned int v = atomicAdd(&g_cnt[b], 1u);
        is_last = (v == 127u);
    }
    __syncthreads();
    if (!is_last) return;

    // last block of this batch: deterministic fixed-order reduction of the
    // 128 partials (L2-hot, 64 KB). Each grp sums 16 partial rows.
    float4 acc = make_float4(0.f, 0.f, 0.f, 0.f);
    const float4* pp = reinterpret_cast<const float4*>(g_pr + (size_t)b * 128 * M);
    #pragma unroll
    for (int j = 0; j < 16; ++j) {
        float4 v = pp[(grp + j * 8) * 32 + m4];
        acc.x += v.x; acc.y += v.y; acc.z += v.z; acc.w += v.w;
    }
    __syncthreads();
    sd[t] = acc;
    __syncthreads();
    #pragma unroll
    for (int s = 4; s > 0; s >>= 1) {
        if (grp < s) {
            float4 o = sd[t + s * 32];
            sd[t].x += o.x; sd[t].y += o.y; sd[t].z += o.z; sd[t].w += o.w;
        }
        __syncthreads();
    }
    if (grp == 0) {
        reinterpret_cast<float4*>(r_out + b * M)[m4] = sd[t];
    }
}

// ---------------- launch ----------------
extern "C" void kernel_launch(void* const* d_in, const int* in_sizes, int n_in,
                              void* d_out, int out_size) {
    const float* memory = (const float*)d_in[0];
    const float* k      = (const float*)d_in[1];
    const float* beta   = (const float*)d_in[2];
    const float* g      = (const float*)d_in[3];
    const float* s      = (const float*)d_in[4];
    const float* gamma  = (const float*)d_in[5];
    const float* w_prev = (const float*)d_in[6];
    const float* e      = (const float*)d_in[7];
    const float* a      = (const float*)d_in[8];

    float* r_out  = (float*)d_out;            // [B, M]
    float* nm_out = (float*)d_out + B * M;    // [B, N, M]

    // kernel 1: one warp per (b,n) row
    cos_kernel<<<(B * N) / 8, 256>>>(memory, k);

    // kernel 2: one block per batch (also resets g_cnt)
    addr_kernel<<<B, 1024>>>(beta, g, s, gamma, w_prev);

    // kernel 3: write + fused deterministic r reduction
    dim3 grid3(N / ROWS_PER_BLK, B);
    write_kernel<<<grid3, 256>>>(memory, e, a, nm_out, r_out);
}

// round 6
// speedup vs baseline: 1.1845x; 1.1457x over previous
#include <cuda_runtime.h>
#include <math.h>

#define B 64
#define N 8192
#define M 128
#define EPS 1e-16f
#define EPS_COS 1e-8f

// ---------------- scratch (no allocation allowed) ----------------
__device__ float g_cos[B * N];            // 2 MB
__device__ float g_w[B * N];              // 2 MB
__device__ float g_pr[B * 128 * M];       // 4 MB partial r: [B][128 blocks][M]
__device__ unsigned int g_cnt[B];         // per-batch completion counters

// ---------------- kernel 1: cosine similarity ----------------
// grid (N/64, B), 256 threads. k-side hoisted to shared (computed once/block).
// Each warp: 4 rows (8 lanes per row), each thread 4 float4 = 64 B of its row.
#define CROWS 64
__global__ __launch_bounds__(256) void cos_kernel(
    const float* __restrict__ mem, const float* __restrict__ k)
{
    __shared__ float4 ks[32];      // k + EPS
    __shared__ float s_invnk;
    int b = blockIdx.y;
    int tid = threadIdx.x;

    if (tid < 32) {
        float4 k4 = reinterpret_cast<const float4*>(k + b * M)[tid];
        k4.x += EPS; k4.y += EPS; k4.z += EPS; k4.w += EPS;
        ks[tid] = k4;
        float nk2 = k4.x * k4.x + k4.y * k4.y + k4.z * k4.z + k4.w * k4.w;
        #pragma unroll
        for (int s = 16; s > 0; s >>= 1) nk2 += __shfl_xor_sync(0xffffffffu, nk2, s);
        if (tid == 0) s_invnk = 1.f / fmaxf(sqrtf(nk2), EPS_COS);
    }
    __syncthreads();

    int warp = tid >> 5, lane = tid & 31;
    int sub = lane >> 3, lane8 = lane & 7;   // 4 row-groups of 8 lanes
    int n0 = blockIdx.x * CROWS;
    float invnk = s_invnk;

    #pragma unroll
    for (int iter = 0; iter < 2; ++iter) {
        int row = n0 + iter * 32 + warp * 4 + sub;
        const float4* mp = reinterpret_cast<const float4*>(
            mem + ((size_t)b * N + row) * M);

        float dot = 0.f, nm2 = 0.f;
        #pragma unroll
        for (int j = 0; j < 4; ++j) {
            float4 m4 = mp[lane8 + j * 8];
            float4 k4 = ks[lane8 + j * 8];
            float mx = m4.x + EPS, my = m4.y + EPS, mz = m4.z + EPS, mw = m4.w + EPS;
            dot += mx * k4.x + my * k4.y + mz * k4.z + mw * k4.w;
            nm2 += mx * mx + my * my + mz * mz + mw * mw;
        }
        // reduce over the 8-lane group (stages 4,2,1 stay within the group)
        #pragma unroll
        for (int s = 4; s > 0; s >>= 1) {
            dot += __shfl_xor_sync(0xffffffffu, dot, s);
            nm2 += __shfl_xor_sync(0xffffffffu, nm2, s);
        }
        if (lane8 == 0) {
            float nm = fmaxf(sqrtf(nm2), EPS_COS);
            g_cos[(size_t)b * N + row] = dot * invnk / nm;
        }
    }
}

// ---------------- kernel 2: softmax + interpolate + shift + sharpen ----------------
// one block per batch, 1024 threads, 8 elems/thread, wg row lives in shared
__global__ __launch_bounds__(1024) void addr_kernel(
    const float* __restrict__ beta, const float* __restrict__ g,
    const float* __restrict__ s, const float* __restrict__ gamma,
    const float* __restrict__ w_prev)
{
    __shared__ float sw[N];        // 32 KB
    __shared__ float red[32];
    int b = blockIdx.x;
    int tid = threadIdx.x;
    int lane = tid & 31, wid = tid >> 5;

    // reset the completion counter for the fused reduction in kernel 3
    if (tid == 0) g_cnt[b] = 0;

    float betav = beta[b], gv = g[b], gammav = gamma[b];
    float s0 = s[b * 3 + 0], s1 = s[b * 3 + 1], s2 = s[b * 3 + 2];

    // pass A: bc = beta*cos into shared, block-max
    float mx = -1e30f;
    #pragma unroll
    for (int j = 0; j < N / 1024; ++j) {
        int i = tid + j * 1024;
        float v = betav * g_cos[b * N + i];
        sw[i] = v;
        mx = fmaxf(mx, v);
    }
    #pragma unroll
    for (int t = 16; t > 0; t >>= 1) mx = fmaxf(mx, __shfl_xor_sync(0xffffffffu, mx, t));
    if (lane == 0) red[wid] = mx;
    __syncthreads();
    float bmx = red[0];
    #pragma unroll
    for (int w = 1; w < 32; ++w) bmx = fmaxf(bmx, red[w]);

    // pass B: exp + sum
    float sum = 0.f;
    #pragma unroll
    for (int j = 0; j < N / 1024; ++j) {
        int i = tid + j * 1024;
        float ev = __expf(sw[i] - bmx);
        sw[i] = ev;
        sum += ev;
    }
    #pragma unroll
    for (int t = 16; t > 0; t >>= 1) sum += __shfl_xor_sync(0xffffffffu, sum, t);
    __syncthreads();
    if (lane == 0) red[wid] = sum;
    __syncthreads();
    float bsum = 0.f;
    #pragma unroll
    for (int w = 0; w < 32; ++w) bsum += red[w];
    float inv = 1.f / bsum;

    // wg = g*wc + (1-g)*w_prev, back into shared
    #pragma unroll
    for (int j = 0; j < N / 1024; ++j) {
        int i = tid + j * 1024;
        sw[i] = gv * (sw[i] * inv) + (1.f - gv) * w_prev[b * N + i];
    }
    __syncthreads();

    // circular shift + pow(gamma); w_hat > 0 always (all inputs positive),
    // so pow(x,y) = exp(y*log(x)) via fast intrinsics is safe.
    float wloc[N / 1024];
    float sum2 = 0.f;
    #pragma unroll
    for (int j = 0; j < N / 1024; ++j) {
        int i = tid + j * 1024;
        int im1 = (i == 0) ? (N - 1) : (i - 1);
        int ip1 = (i == N - 1) ? 0 : (i + 1);
        float wh = s0 * sw[im1] + s1 * sw[i] + s2 * sw[ip1];
        float ww = __expf(gammav * __logf(wh));
        wloc[j] = ww;
        sum2 += ww;
    }
    #pragma unroll
    for (int t = 16; t > 0; t >>= 1) sum2 += __shfl_xor_sync(0xffffffffu, sum2, t);
    __syncthreads();
    if (lane == 0) red[wid] = sum2;
    __syncthreads();
    float bsum2 = 0.f;
    #pragma unroll
    for (int w = 0; w < 32; ++w) bsum2 += red[w];
    float inv2 = 1.f / (bsum2 + EPS);

    #pragma unroll
    for (int j = 0; j < N / 1024; ++j) {
        int i = tid + j * 1024;
        g_w[b * N + i] = wloc[j] * inv2;
    }
}

// ---------------- kernel 3: new_mem write + fused r reduction ----------------
// grid (128, B), 256 threads; each block: 64 rows of one batch.
// Last-finishing block per batch deterministically sums the 128 partials.
#define ROWS_PER_BLK 64
__global__ __launch_bounds__(256) void write_kernel(
    const float* __restrict__ mem, const float* __restrict__ e,
    const float* __restrict__ a, float* __restrict__ newmem,
    float* __restrict__ r_out)
{
    int b = blockIdx.y;
    int blk = blockIdx.x;              // 0..127
    int t = threadIdx.x;
    int m4 = t & 31;                   // float4 index along M
    int grp = t >> 5;                  // 8 row groups

    const float4 e4 = reinterpret_cast<const float4*>(e + b * M)[m4];
    const float4 a4 = reinterpret_cast<const float4*>(a + b * M)[m4];

    int n0 = blk * ROWS_PER_BLK;
    size_t base = ((size_t)b * N + n0) * M;
    const float4* mp = reinterpret_cast<const float4*>(mem + base);
    float4* op = reinterpret_cast<float4*>(newmem + base);
    const float* wp = g_w + b * N + n0;

    float4 racc = make_float4(0.f, 0.f, 0.f, 0.f);
    #pragma unroll
    for (int it = 0; it < ROWS_PER_BLK / 8; ++it) {
        int row = it * 8 + grp;
        float wv = __ldg(wp + row);
        float4 mv = mp[row * 32 + m4];
        float4 o;
        o.x = mv.x * (1.f - wv * e4.x) + wv * a4.x;
        o.y = mv.y * (1.f - wv * e4.y) + wv * a4.y;
        o.z = mv.z * (1.f - wv * e4.z) + wv * a4.z;
        o.w = mv.w * (1.f - wv * e4.w) + wv * a4.w;
        op[row * 32 + m4] = o;
        racc.x += wv * mv.x;
        racc.y += wv * mv.y;
        racc.z += wv * mv.z;
        racc.w += wv * mv.w;
    }

    __shared__ float4 sd[256];
    __shared__ bool is_last;
    sd[t] = racc;
    __syncthreads();
    #pragma unroll
    for (int s = 4; s > 0; s >>= 1) {
        if (grp < s) {
            float4 o = sd[t + s * 32];
            sd[t].x += o.x; sd[t].y += o.y; sd[t].z += o.z; sd[t].w += o.w;
        }
        __syncthreads();
    }
    if (grp == 0) {
        reinterpret_cast<float4*>(g_pr + ((size_t)b * 128 + blk) * M)[m4] = sd[t];
    }

    // make the partial visible, then take a ticket
    __threadfence();
    if (t == 0) {
        unsigned int v = atomicAdd(&g_cnt[b], 1u);
        is_last = (v == 127u);
    }
    __syncthreads();
    if (!is_last) return;

    // last block of this batch: deterministic fixed-order reduction of the
    // 128 partials (L2-hot, 64 KB). Each grp sums 16 partial rows.
    float4 acc = make_float4(0.f, 0.f, 0.f, 0.f);
    const float4* pp = reinterpret_cast<const float4*>(g_pr + (size_t)b * 128 * M);
    #pragma unroll
    for (int j = 0; j < 16; ++j) {
        float4 v = pp[(grp + j * 8) * 32 + m4];
        acc.x += v.x; acc.y += v.y; acc.z += v.z; acc.w += v.w;
    }
    __syncthreads();
    sd[t] = acc;
    __syncthreads();
    #pragma unroll
    for (int s = 4; s > 0; s >>= 1) {
        if (grp < s) {
            float4 o = sd[t + s * 32];
            sd[t].x += o.x; sd[t].y += o.y; sd[t].z += o.z; sd[t].w += o.w;
        }
        __syncthreads();
    }
    if (grp == 0) {
        reinterpret_cast<float4*>(r_out + b * M)[m4] = sd[t];
    }
}

// ---------------- launch ----------------
extern "C" void kernel_launch(void* const* d_in, const int* in_sizes, int n_in,
                              void* d_out, int out_size) {
    const float* memory = (const float*)d_in[0];
    const float* k      = (const float*)d_in[1];
    const float* beta   = (const float*)d_in[2];
    const float* g      = (const float*)d_in[3];
    const float* s      = (const float*)d_in[4];
    const float* gamma  = (const float*)d_in[5];
    const float* w_prev = (const float*)d_in[6];
    const float* e      = (const float*)d_in[7];
    const float* a      = (const float*)d_in[8];

    float* r_out  = (float*)d_out;            // [B, M]
    float* nm_out = (float*)d_out + B * M;    // [B, N, M]

    // kernel 1: cosine similarity (k-side hoisted, 8-lane row groups)
    dim3 grid1(N / CROWS, B);
    cos_kernel<<<grid1, 256>>>(memory, k);

    // kernel 2: one block per batch (also resets g_cnt)
    addr_kernel<<<B, 1024>>>(beta, g, s, gamma, w_prev);

    // kernel 3: write + fused deterministic r reduction
    dim3 grid3(N / ROWS_PER_BLK, B);
    write_kernel<<<grid3, 256>>>(memory, e, a, nm_out, r_out);
}